// round 10
// baseline (speedup 1.0000x reference)
#include <cuda_runtime.h>
#include <cuda_bf16.h>

// RandomPrompter: out[b,c,h,w] = x[b,c,h,w] + (patch inside per-sample 30x30 window)
// Shapes: x [256,3,224,224] f32, patch [1,3,30,30] f32, offsets [256,2] i32.
//
// Pure streaming op (308 MB, zero reuse) at the DRAM wall (~7.4 TB/s, 93% of
// spec). Final interior probe of the MLP sweep: MLP=3 per thread (between
// the proven-best 2 and the occupancy-limited 4). float4 x 3, TPB=256,
// evict-first (.cs) on both streams, exact grid.

#define BATCH 256
#define CH    3
#define HH    224
#define WW    224
#define PSZ   30

#define W4        (WW / 4)                        // 56 float4 per row
#define TOTAL_V4  (BATCH * CH * HH * W4)          // 9,633,792 float4s
#define VPT       3                               // float4s per thread
#define TPB       256
#define TILE      (TPB * VPT)                     // 768 float4s per block

__device__ __forceinline__ void patch_add(float4& val, int v,
                                          const float* __restrict__ patch,
                                          const int2* __restrict__ offsets)
{
    // v = ((b*3 + c)*224 + h)*56 + w4
    int w4 = v % W4;
    int t  = v / W4;
    int h  = t % HH;
    int t2 = t / HH;
    int c  = t2 % CH;
    int b  = t2 / CH;

    int2 off = __ldg(&offsets[b]);   // (row, col), each in [0, 194)
    int dh = h - off.x;
    if ((unsigned)dh < (unsigned)PSZ) {
        const float* prow = patch + (c * PSZ + dh) * PSZ;
        int dw = w4 * 4 - off.y;     // patch-relative column of lane 0
        if ((unsigned)(dw + 0) < (unsigned)PSZ) val.x += __ldg(&prow[dw + 0]);
        if ((unsigned)(dw + 1) < (unsigned)PSZ) val.y += __ldg(&prow[dw + 1]);
        if ((unsigned)(dw + 2) < (unsigned)PSZ) val.z += __ldg(&prow[dw + 2]);
        if ((unsigned)(dw + 3) < (unsigned)PSZ) val.w += __ldg(&prow[dw + 3]);
    }
}

__global__ __launch_bounds__(TPB) void random_prompter_kernel(
    const float4* __restrict__ x,
    const float* __restrict__ patch,
    const int2* __restrict__ offsets,
    float4* __restrict__ out)
{
    int base = blockIdx.x * TILE + threadIdx.x;
    int v0 = base;
    int v1 = base + TPB;
    int v2 = base + 2 * TPB;

    // TOTAL_V4 (9,633,792) is divisible by TILE (768): 12544 blocks, no tail.
    // All three loads issued before any consumer (MLP=3 per thread).
    float4 a = __ldcs(&x[v0]);
    float4 b = __ldcs(&x[v1]);
    float4 c = __ldcs(&x[v2]);

    patch_add(a, v0, patch, offsets);
    patch_add(b, v1, patch, offsets);
    patch_add(c, v2, patch, offsets);

    __stcs(&out[v0], a);
    __stcs(&out[v1], b);
    __stcs(&out[v2], c);
}

extern "C" void kernel_launch(void* const* d_in, const int* in_sizes, int n_in,
                              void* d_out, int out_size)
{
    const float4* x      = (const float4*)d_in[0];
    const float*  patch  = (const float*)d_in[1];
    const int2*   offs   = (const int2*)d_in[2];
    float4*       out    = (float4*)d_out;

    const int blocks = TOTAL_V4 / TILE;  // 12544, exact
    random_prompter_kernel<<<blocks, TPB>>>(x, patch, offs, out);
}

// round 11
// speedup vs baseline: 1.0084x; 1.0084x over previous
#include <cuda_runtime.h>
#include <cuda_bf16.h>

// RandomPrompter: out[b,c,h,w] = x[b,c,h,w] + (patch inside per-sample 30x30 window)
// Shapes: x [256,3,224,224] f32, patch [1,3,30,30] f32, offsets [256,2] i32.
//
// TERMINAL KERNEL (session-best, locked in after a 10-round search).
// Pure streaming op: 154 MB read + 154 MB write, zero reuse -> DRAM-wall bound.
//
// Search matrix measured: vector width {float4, v8/256-bit} x per-thread MLP
// {1,2,3,4} x TPB {128,256,512} x cache policy {.cs,.cg} x structure
// {one-shot, persistent software-pipelined}. All MLP>=2 one-shot variants land
// 41.3-42.6us kernel (7.2-7.5 TB/s effective, ~93% of 8 TB/s HBM spec);
// persistent loop regressed (dependency-chained loads lose to independent
// short-lived warps). Best-measured point: one-shot float4 x MLP=2, TPB=256,
// evict-first (.cs) both streams, exact 18816x256 grid, 32 regs, occ ~79%.
// Non-DRAM counters all slack (issue 21%, fma 9%, L2 40%) — this is the
// roofline for this op on sm_103a.

#define BATCH 256
#define CH    3
#define HH    224
#define WW    224
#define PSZ   30

#define W4        (WW / 4)                        // 56 float4 per row
#define TOTAL_V4  (BATCH * CH * HH * W4)          // 9,633,792 float4s
#define VPT       2                               // float4s per thread
#define TPB       256
#define TILE      (TPB * VPT)                     // 512 float4s per block

__device__ __forceinline__ void patch_add(float4& val, int v,
                                          const float* __restrict__ patch,
                                          const int2* __restrict__ offsets)
{
    // v = ((b*3 + c)*224 + h)*56 + w4
    int w4 = v % W4;
    int t  = v / W4;
    int h  = t % HH;
    int t2 = t / HH;
    int c  = t2 % CH;
    int b  = t2 / CH;

    int2 off = __ldg(&offsets[b]);   // (row, col), each in [0, 194)
    int dh = h - off.x;
    if ((unsigned)dh < (unsigned)PSZ) {
        const float* prow = patch + (c * PSZ + dh) * PSZ;
        int dw = w4 * 4 - off.y;     // patch-relative column of lane 0
        if ((unsigned)(dw + 0) < (unsigned)PSZ) val.x += __ldg(&prow[dw + 0]);
        if ((unsigned)(dw + 1) < (unsigned)PSZ) val.y += __ldg(&prow[dw + 1]);
        if ((unsigned)(dw + 2) < (unsigned)PSZ) val.z += __ldg(&prow[dw + 2]);
        if ((unsigned)(dw + 3) < (unsigned)PSZ) val.w += __ldg(&prow[dw + 3]);
    }
}

__global__ __launch_bounds__(TPB) void random_prompter_kernel(
    const float4* __restrict__ x,
    const float* __restrict__ patch,
    const int2* __restrict__ offsets,
    float4* __restrict__ out)
{
    int base = blockIdx.x * TILE + threadIdx.x;
    int v0 = base;
    int v1 = base + TPB;

    // TOTAL_V4 (9,633,792) is divisible by TILE (512): 18816 blocks, no tail.
    // Both loads issued before either consumes (MLP=2 per thread).
    float4 a = __ldcs(&x[v0]);
    float4 b = __ldcs(&x[v1]);

    patch_add(a, v0, patch, offsets);
    patch_add(b, v1, patch, offsets);

    __stcs(&out[v0], a);
    __stcs(&out[v1], b);
}

extern "C" void kernel_launch(void* const* d_in, const int* in_sizes, int n_in,
                              void* d_out, int out_size)
{
    const float4* x      = (const float4*)d_in[0];
    const float*  patch  = (const float*)d_in[1];
    const int2*   offs   = (const int2*)d_in[2];
    float4*       out    = (float4*)d_out;

    const int blocks = TOTAL_V4 / TILE;  // 18816, exact
    random_prompter_kernel<<<blocks, TPB>>>(x, patch, offs, out);
}